// round 17
// baseline (speedup 1.0000x reference)
#include <cuda_runtime.h>
#include <math.h>

constexpr int Bn   = 64;
constexpr int Hn   = 512;
constexpr int Wn   = 512;
constexpr int NPTS = 512;
constexpr int HWn  = Hn * Wn;
constexpr int SLICES = 16;                  // blocks per image
constexpr int RB = Bn * SLICES;             // 1024 blocks
constexpr int PPB = NPTS / SLICES;          // 32 points owned per block
constexpr float SCALE = 0.25f;              // 512/2048
constexpr double CELL_AREA = 16.0;

// zero-initialized accumulators; reset by the winner block each call
__device__ double g_S[Bn], g_Q[Bn], g_T[Bn], g_A[Bn], g_C[Bn];
__device__ unsigned g_done;

__device__ __forceinline__ float wgt_of(int r2) {
    return r2 == 0 ? 1.0f : (r2 == 1 ? 0.60653066f : 0.49306869f);
}

__global__ void __launch_bounds__(256, 7)
k_all(const float* __restrict__ pred, const float* __restrict__ points,
      float* __restrict__ out) {
    const int tid = threadIdx.x;
    const int b = blockIdx.x >> 4;
    const int slice = blockIdx.x & (SLICES - 1);
    const int i0 = slice * PPB;             // first owned point

    // ---- phase 0: all 512 cell coords of image b -> smem (packed) ----
    __shared__ int s_xy[NPTS];
    {
        // thread tid loads points 2*tid, 2*tid+1 as one float4
        float4 pv = reinterpret_cast<const float4*>(points)
                    [(size_t)b * (NPTS / 2) + tid];
        int x0 = (int)fminf(fmaxf(pv.x * SCALE, 0.f), (float)(Wn - 1));
        int y0 = (int)fminf(fmaxf(pv.y * SCALE, 0.f), (float)(Hn - 1));
        int x1 = (int)fminf(fmaxf(pv.z * SCALE, 0.f), (float)(Wn - 1));
        int y1 = (int)fminf(fmaxf(pv.w * SCALE, 0.f), (float)(Hn - 1));
        s_xy[2 * tid + 0] = x0 | (y0 << 16);
        s_xy[2 * tid + 1] = x1 | (y1 << 16);
    }
    __syncthreads();

    // ---- phase 1: stream S,Q over my slice (16 float4/thread, 8-deep) ----
    constexpr int CH = HWn / 4 / SLICES;    // 4096 float4 per block
    const float4* p = reinterpret_cast<const float4*>(pred)
                      + (size_t)b * (HWn / 4) + (size_t)slice * CH;
    float s = 0.f, q = 0.f;
    #pragma unroll
    for (int it = 0; it < 2; ++it) {
        float4 v[8];
        #pragma unroll
        for (int j = 0; j < 8; ++j)
            v[j] = p[(it * 8 + j) * 256 + tid];
        #pragma unroll
        for (int j = 0; j < 8; ++j) {
            s += (v[j].x + v[j].y) + (v[j].z + v[j].w);
            q += v[j].x * v[j].x + v[j].y * v[j].y
               + v[j].z * v[j].z + v[j].w * v[j].w;
        }
    }

    // ---- phase 2: own 32 points — T, A (gathers), self-C ----
    float tw = 0.f, ta = 0.f, tc = 0.f;
    const float* pb = pred + (size_t)b * HWn;
    for (int u = tid; u < PPB * 9; u += 256) {
        int pl  = u / 9;
        int tap = u - pl * 9;
        int pk = s_xy[i0 + pl];
        int x = pk & 0xffff, y = pk >> 16;
        int dy = tap / 3 - 1;
        int dx = tap - (tap / 3) * 3 - 1;
        int ny = y + dy, nx = x + dx;
        if ((unsigned)ny < (unsigned)Hn && (unsigned)nx < (unsigned)Wn) {
            float w = wgt_of(dy * dy + dx * dx);
            tw += w;
            tc += w * w;
            ta += w * __ldg(&pb[ny * Wn + nx]);
        }
    }

    // ---- phase 3: cross-C — pairs (i in own range, j > i) ----
    float cc = 0.f;
    for (int ii = 0; ii < PPB; ++ii) {
        int i = i0 + ii;
        int pi = s_xy[i];
        int xi = pi & 0xffff, yi = pi >> 16;
        for (int j = i + 1 + tid; j < NPTS; j += 256) {
            int pj = s_xy[j];
            unsigned v = __vabsdiffu2((unsigned)pi, (unsigned)pj);
            if ((v & 0xfffcfffcu) != 0u) continue;   // fast reject (diff > 3)
            int xj = pj & 0xffff, yj = pj >> 16;
            int adx = xj - xi; adx = adx < 0 ? -adx : adx;
            int ady = yj - yi; ady = ady < 0 ? -ady : ady;
            if (adx > 2 || ady > 2) continue;
            #pragma unroll
            for (int dy = -1; dy <= 1; ++dy) {
                int ny = yi + dy;
                if ((unsigned)ny >= (unsigned)Hn) continue;
                int qdy = ny - yj;
                if (qdy < -1 || qdy > 1) continue;
                #pragma unroll
                for (int dx = -1; dx <= 1; ++dx) {
                    int nx = xi + dx;
                    if ((unsigned)nx >= (unsigned)Wn) continue;
                    int qdx = nx - xj;
                    if (qdx < -1 || qdx > 1) continue;
                    cc += wgt_of(dy * dy + dx * dx)
                        * wgt_of(qdy * qdy + qdx * qdx);
                }
            }
        }
    }
    tc += 2.f * cc;

    // ---- block reduce 5 accumulators ----
    #pragma unroll
    for (int o = 16; o; o >>= 1) {
        s  += __shfl_down_sync(0xffffffffu, s,  o);
        q  += __shfl_down_sync(0xffffffffu, q,  o);
        tw += __shfl_down_sync(0xffffffffu, tw, o);
        ta += __shfl_down_sync(0xffffffffu, ta, o);
        tc += __shfl_down_sync(0xffffffffu, tc, o);
    }
    __shared__ float sh[5][8];
    __shared__ int s_win;
    int lane = tid & 31, wid = tid >> 5;
    if (lane == 0) {
        sh[0][wid] = s; sh[1][wid] = q; sh[2][wid] = tw;
        sh[3][wid] = ta; sh[4][wid] = tc;
    }
    __syncthreads();
    if (tid == 0) {
        float S = 0.f, Q = 0.f, Tw = 0.f, Ta = 0.f, Tc = 0.f;
        #pragma unroll
        for (int j = 0; j < 8; ++j) {
            S += sh[0][j]; Q += sh[1][j]; Tw += sh[2][j];
            Ta += sh[3][j]; Tc += sh[4][j];
        }
        // returning atomics: results arrive only after the L2 RMW commits
        double o0 = atomicAdd(&g_S[b], (double)S);
        double o1 = atomicAdd(&g_Q[b], (double)Q);
        double o2 = atomicAdd(&g_T[b], (double)Tw);
        double o3 = atomicAdd(&g_A[b], (double)Ta);
        double o4 = atomicAdd(&g_C[b], (double)Tc);
        // data-dependency (never true) orders the counter after the adds
        unsigned dep = (o0 + o1 + o2 + o3 + o4 == -1.0) ? 1u : 0u;
        unsigned old = atomicAdd(&g_done, 1u + dep);
        s_win = (old == (unsigned)RB - 1u) ? 1 : 0;
    }
    __syncthreads();
    if (!s_win) return;

    // ---- winner (last arriving block): finalize + reset ----
    double cnt = 0.0, sp = 0.0;
    if (tid < Bn) {
        double S = atomicAdd(&g_S[tid], 0.0);   // coherent L2 reads
        double Q = atomicAdd(&g_Q[tid], 0.0);
        double T = atomicAdd(&g_T[tid], 0.0);
        double A = atomicAdd(&g_A[tid], 0.0);
        double C = atomicAdd(&g_C[tid], 0.0);
        cnt = fabs(S / CELL_AREA - (double)NPTS);
        double Sp = S + 1e-8;
        sp = (Q / (Sp * Sp) - 2.0 * A / (Sp * T) + C / (T * T)) / (double)HWn;
        g_S[tid] = 0.0; g_Q[tid] = 0.0; g_T[tid] = 0.0;
        g_A[tid] = 0.0; g_C[tid] = 0.0;
    }
    #pragma unroll
    for (int o = 16; o; o >>= 1) {
        cnt += __shfl_down_sync(0xffffffffu, cnt, o);
        sp  += __shfl_down_sync(0xffffffffu, sp, o);
    }
    __shared__ double sc[2], ssp[2];
    if (wid < 2 && lane == 0) { sc[wid] = cnt; ssp[wid] = sp; }
    __syncthreads();
    if (tid == 0) {
        g_done = 0u;
        double count_loss = (sc[0] + sc[1]) / (double)Bn;
        double spatial    = (ssp[0] + ssp[1]) / (double)Bn;
        out[0] = (float)(2.5 * count_loss + 0.1 * spatial);
        out[1] = (float)count_loss;
        out[2] = (float)spatial;
    }
}

extern "C" void kernel_launch(void* const* d_in, const int* in_sizes, int n_in,
                              void* d_out, int out_size) {
    const float* pred   = (const float*)d_in[0];
    const float* points = (const float*)d_in[1];
    float* out = (float*)d_out;
    k_all<<<RB, 256>>>(pred, points, out);
}